// round 1
// baseline (speedup 1.0000x reference)
#include <cuda_runtime.h>
#include <math.h>

#define B 4
#define S 2048
#define D 1024
#define H 16
#define DH 64

// Scratch (allocation-free rule: __device__ globals)
__device__ float g_Qp[B*S*D];
__device__ float g_Kp[B*S*D];
__device__ float g_Vp[B*S*D];
__device__ float g_Ctx[B*S*D];

// ---------------------------------------------------------------------------
// Linear: out[M,N] = X[M,K] @ W[N,K]^T + bias[N]   (torch Linear semantics)
// Tiles: 128x128x16, 256 threads, 8x8 per thread.
// ---------------------------------------------------------------------------
#define GBM 128
#define GBN 128
#define GBK 16

__global__ __launch_bounds__(256) void linear_kernel(
    const float* __restrict__ X, const float* __restrict__ W,
    const float* __restrict__ bias, float* __restrict__ out,
    int M, int N, int K)
{
    __shared__ float Xs[GBK][GBM + 4];
    __shared__ float Ws[GBK][GBN + 4];

    const int tid = threadIdx.x;
    const int tx = tid & 15;
    const int ty = tid >> 4;
    const int m0 = blockIdx.y * GBM;
    const int n0 = blockIdx.x * GBN;

    float acc[8][8];
    #pragma unroll
    for (int i = 0; i < 8; i++)
        #pragma unroll
        for (int j = 0; j < 8; j++) acc[i][j] = 0.0f;

    for (int k0 = 0; k0 < K; k0 += GBK) {
        // Load X tile (128x16) and W tile (128x16), float4 per thread x2.
        #pragma unroll
        for (int i = 0; i < 2; i++) {
            int idx = tid + i * 256;      // 0..511 float4 slots
            int row = idx >> 2;           // 0..127
            int c4  = idx & 3;            // 0..3
            float4 xv = *(const float4*)(X + (size_t)(m0 + row) * K + k0 + c4 * 4);
            Xs[c4*4+0][row] = xv.x; Xs[c4*4+1][row] = xv.y;
            Xs[c4*4+2][row] = xv.z; Xs[c4*4+3][row] = xv.w;
            float4 wv = *(const float4*)(W + (size_t)(n0 + row) * K + k0 + c4 * 4);
            Ws[c4*4+0][row] = wv.x; Ws[c4*4+1][row] = wv.y;
            Ws[c4*4+2][row] = wv.z; Ws[c4*4+3][row] = wv.w;
        }
        __syncthreads();

        #pragma unroll
        for (int kk = 0; kk < GBK; kk++) {
            float a[8], b[8];
            #pragma unroll
            for (int i = 0; i < 8; i++) a[i] = Xs[kk][ty*8 + i];
            #pragma unroll
            for (int j = 0; j < 8; j++) b[j] = Ws[kk][tx*8 + j];
            #pragma unroll
            for (int i = 0; i < 8; i++)
                #pragma unroll
                for (int j = 0; j < 8; j++)
                    acc[i][j] += a[i] * b[j];
        }
        __syncthreads();
    }

    #pragma unroll
    for (int i = 0; i < 8; i++) {
        int m = m0 + ty*8 + i;
        #pragma unroll
        for (int j = 0; j < 8; j++) {
            int n = n0 + tx*8 + j;
            out[(size_t)m * N + n] = acc[i][j] + bias[n];
        }
    }
}

// ---------------------------------------------------------------------------
// Flash-style causal attention.
// Layouts: Qp/Kp/Vp/Ctx are [B, S, D] with head h occupying cols [h*DH, h*DH+DH).
// Block: one (b, h, q-tile of 64 rows). 256 threads.
// K-tile = 32 to stay under the 48KB static smem limit.
// ---------------------------------------------------------------------------
#define QT 64
#define KT 32

__global__ __launch_bounds__(256) void attn_kernel(
    const float* __restrict__ Qp, const float* __restrict__ Kp,
    const float* __restrict__ Vp, float* __restrict__ Ctx)
{
    __shared__ float Qs[QT][DH + 1];
    __shared__ float Ks[KT][DH + 1];
    __shared__ float Vs[KT][DH + 1];
    __shared__ float Ss[QT][KT + 1];
    __shared__ float rowm[QT], rowl[QT], rowa[QT];

    const int tid = threadIdx.x;
    const int tx = tid & 15;
    const int ty = tid >> 4;
    const int q0 = blockIdx.x * QT;
    const int h  = blockIdx.y;
    const int b  = blockIdx.z;

    const size_t base = ((size_t)b * S) * D + (size_t)h * DH;

    // Load Q tile, pre-scaled by 1/sqrt(DH) = 0.125
    #pragma unroll
    for (int i = 0; i < 4; i++) {
        int idx = tid + i * 256;      // 1024 float4 slots (64 rows x 16)
        int row = idx >> 4;
        int c4  = idx & 15;
        float4 v = *(const float4*)(Qp + base + (size_t)(q0 + row) * D + c4 * 4);
        const float sc = 0.125f;
        Qs[row][c4*4+0] = v.x * sc; Qs[row][c4*4+1] = v.y * sc;
        Qs[row][c4*4+2] = v.z * sc; Qs[row][c4*4+3] = v.w * sc;
    }
    if (tid < QT) { rowm[tid] = -1e30f; rowl[tid] = 0.0f; }

    float ctx[4][4];
    #pragma unroll
    for (int i = 0; i < 4; i++)
        #pragma unroll
        for (int j = 0; j < 4; j++) ctx[i][j] = 0.0f;

    __syncthreads();

    // Causal: q rows cover [q0, q0+63]; need k tiles with k0 < q0 + QT.
    for (int k0 = 0; k0 < q0 + QT; k0 += KT) {
        // Load K/V tiles (32 rows x 64)
        #pragma unroll
        for (int i = 0; i < 2; i++) {
            int idx = tid + i * 256;  // 512 float4 slots
            int row = idx >> 4;
            int c4  = idx & 15;
            float4 kv = *(const float4*)(Kp + base + (size_t)(k0 + row) * D + c4 * 4);
            Ks[row][c4*4+0] = kv.x; Ks[row][c4*4+1] = kv.y;
            Ks[row][c4*4+2] = kv.z; Ks[row][c4*4+3] = kv.w;
            float4 vv = *(const float4*)(Vp + base + (size_t)(k0 + row) * D + c4 * 4);
            Vs[row][c4*4+0] = vv.x; Vs[row][c4*4+1] = vv.y;
            Vs[row][c4*4+2] = vv.z; Vs[row][c4*4+3] = vv.w;
        }
        __syncthreads();

        // S = Qs @ Ks^T : thread covers rows ty*4+i, cols tx*2+j
        float sc4[4][2];
        #pragma unroll
        for (int i = 0; i < 4; i++) { sc4[i][0] = 0.0f; sc4[i][1] = 0.0f; }
        #pragma unroll 16
        for (int d = 0; d < DH; d++) {
            float a0 = Qs[ty*4+0][d], a1 = Qs[ty*4+1][d];
            float a2 = Qs[ty*4+2][d], a3 = Qs[ty*4+3][d];
            float b0 = Ks[tx*2+0][d], b1 = Ks[tx*2+1][d];
            sc4[0][0] += a0*b0; sc4[0][1] += a0*b1;
            sc4[1][0] += a1*b0; sc4[1][1] += a1*b1;
            sc4[2][0] += a2*b0; sc4[2][1] += a2*b1;
            sc4[3][0] += a3*b0; sc4[3][1] += a3*b1;
        }
        #pragma unroll
        for (int i = 0; i < 4; i++) {
            int qr = ty*4 + i;
            #pragma unroll
            for (int j = 0; j < 2; j++) {
                int kc = tx*2 + j;
                float v = sc4[i][j];
                if (k0 + kc > q0 + qr) v = -1e30f;   // causal mask
                Ss[qr][kc] = v;
            }
        }
        __syncthreads();

        // Online softmax per row (threads 0..63)
        if (tid < QT) {
            int r = tid;
            float mold = rowm[r];
            float mx = mold;
            #pragma unroll
            for (int c = 0; c < KT; c++) mx = fmaxf(mx, Ss[r][c]);
            float alpha = __expf(mold - mx);
            float l = rowl[r] * alpha;
            #pragma unroll
            for (int c = 0; c < KT; c++) {
                float p = __expf(Ss[r][c] - mx);
                Ss[r][c] = p;
                l += p;
            }
            rowm[r] = mx; rowl[r] = l; rowa[r] = alpha;
        }
        __syncthreads();

        // ctx = ctx*alpha + P @ Vs : thread covers rows ty*4+i, dcols tx*4+j
        float al[4];
        #pragma unroll
        for (int i = 0; i < 4; i++) al[i] = rowa[ty*4 + i];
        #pragma unroll
        for (int i = 0; i < 4; i++)
            #pragma unroll
            for (int j = 0; j < 4; j++) ctx[i][j] *= al[i];

        #pragma unroll 8
        for (int kk = 0; kk < KT; kk++) {
            float p0 = Ss[ty*4+0][kk], p1 = Ss[ty*4+1][kk];
            float p2 = Ss[ty*4+2][kk], p3 = Ss[ty*4+3][kk];
            float v0 = Vs[kk][tx*4+0], v1 = Vs[kk][tx*4+1];
            float v2 = Vs[kk][tx*4+2], v3 = Vs[kk][tx*4+3];
            ctx[0][0] += p0*v0; ctx[0][1] += p0*v1; ctx[0][2] += p0*v2; ctx[0][3] += p0*v3;
            ctx[1][0] += p1*v0; ctx[1][1] += p1*v1; ctx[1][2] += p1*v2; ctx[1][3] += p1*v3;
            ctx[2][0] += p2*v0; ctx[2][1] += p2*v1; ctx[2][2] += p2*v2; ctx[2][3] += p2*v3;
            ctx[3][0] += p3*v0; ctx[3][1] += p3*v1; ctx[3][2] += p3*v2; ctx[3][3] += p3*v3;
        }
        __syncthreads();   // protect Ks/Vs/Ss before next tile's loads
    }

    // Normalize and write out in [B,S,D] layout (head-interleaved)
    #pragma unroll
    for (int i = 0; i < 4; i++) {
        int qr = ty*4 + i;
        float linv = 1.0f / rowl[qr];
        #pragma unroll
        for (int j = 0; j < 4; j++) {
            Ctx[base + (size_t)(q0 + qr) * D + tx*4 + j] = ctx[i][j] * linv;
        }
    }
}

// ---------------------------------------------------------------------------
// Launch
// Inputs (metadata order): q,k,v,mask,wq,bq,wk,bk,wv,bv,wo,bo
// mask is the causal tril by construction; causality is computed in-kernel.
// ---------------------------------------------------------------------------
extern "C" void kernel_launch(void* const* d_in, const int* in_sizes, int n_in,
                              void* d_out, int out_size)
{
    (void)in_sizes; (void)n_in; (void)out_size;
    const float* q  = (const float*)d_in[0];
    const float* k  = (const float*)d_in[1];
    const float* v  = (const float*)d_in[2];
    const float* wq = (const float*)d_in[4];
    const float* bq = (const float*)d_in[5];
    const float* wk = (const float*)d_in[6];
    const float* bk = (const float*)d_in[7];
    const float* wv = (const float*)d_in[8];
    const float* bv = (const float*)d_in[9];
    const float* wo = (const float*)d_in[10];
    const float* bo = (const float*)d_in[11];
    float* out = (float*)d_out;

    float *Qp, *Kp, *Vp, *Ctx;
    cudaGetSymbolAddress((void**)&Qp,  g_Qp);
    cudaGetSymbolAddress((void**)&Kp,  g_Kp);
    cudaGetSymbolAddress((void**)&Vp,  g_Vp);
    cudaGetSymbolAddress((void**)&Ctx, g_Ctx);

    const int M = B * S;   // 8192
    dim3 gthr(256);
    dim3 ggrid(D / GBN, M / GBM);     // (8, 64)

    linear_kernel<<<ggrid, gthr>>>(q, wq, bq, Qp, M, D, D);
    linear_kernel<<<ggrid, gthr>>>(k, wk, bk, Kp, M, D, D);
    linear_kernel<<<ggrid, gthr>>>(v, wv, bv, Vp, M, D, D);

    dim3 agrid(S / QT, H, B);         // (32, 16, 4)
    attn_kernel<<<agrid, gthr>>>(Qp, Kp, Vp, Ctx);

    linear_kernel<<<ggrid, gthr>>>(Ctx, wo, bo, out, M, D, D);
}

// round 3
// speedup vs baseline: 2.4322x; 2.4322x over previous
#include <cuda_runtime.h>
#include <cstdint>

#define B 4
#define S 2048
#define D 1024
#define H 16
#define DH 64

// Scratch (allocation-free rule: __device__ globals)
__device__ float g_Qp[B*S*D];
__device__ float g_Kp[B*S*D];
__device__ float g_Vp[B*S*D];
__device__ float g_Ctx[B*S*D];

// ---------------------------------------------------------------------------
// Helpers
// ---------------------------------------------------------------------------
__device__ __forceinline__ uint32_t f2tf32(float f) {
    uint32_t r; asm("cvt.rna.tf32.f32 %0, %1;" : "=r"(r) : "f"(f)); return r;
}
__device__ __forceinline__ float f2tf32f(float f) {
    return __uint_as_float(f2tf32(f));
}
__device__ __forceinline__ uint32_t smem_u32(const void* p) {
    uint32_t a;
    asm("{ .reg .u64 t; cvta.to.shared.u64 t, %1; cvt.u32.u64 %0, t; }"
        : "=r"(a) : "l"(p));
    return a;
}
// D = A(16x8) @ B(8x8) + D, tf32 inputs (b32 regs), f32 accum
__device__ __forceinline__ void mma8(float* c, const uint32_t* a, const uint32_t* b) {
    asm volatile(
        "mma.sync.aligned.m16n8k8.row.col.f32.tf32.tf32.f32 "
        "{%0,%1,%2,%3}, {%4,%5,%6,%7}, {%8,%9}, {%0,%1,%2,%3};"
        : "+f"(c[0]), "+f"(c[1]), "+f"(c[2]), "+f"(c[3])
        : "r"(a[0]), "r"(a[1]), "r"(a[2]), "r"(a[3]), "r"(b[0]), "r"(b[1]));
}
__device__ __forceinline__ void cp_async16(uint32_t dst, const void* src) {
    asm volatile("cp.async.ca.shared.global [%0], [%1], 16;"
                 :: "r"(dst), "l"(src));
}
__device__ __forceinline__ void cp_commit() {
    asm volatile("cp.async.commit_group;");
}
__device__ __forceinline__ void cp_wait1() {
    asm volatile("cp.async.wait_group 1;" ::: "memory");
}
__device__ __forceinline__ void cp_wait0() {
    asm volatile("cp.async.wait_group 0;" ::: "memory");
}

// ---------------------------------------------------------------------------
// Linear via mma.sync tf32: out[M,N] = X[M,K] @ W[N,K]^T + bias[N]
// CTA tile 128x128, k-chunk 16, cp.async double buffer.
// 8 warps: warp_m = wid&1 (64 rows), warp_n = wid>>1 (32 cols).
// Per warp: 4 m-tiles x 4 n-tiles of m16n8k8.
// ---------------------------------------------------------------------------
#define LKC 16

__global__ __launch_bounds__(256) void linear_mma_kernel(
    const float* __restrict__ X, const float* __restrict__ Wt,
    const float* __restrict__ bias, float* __restrict__ out)
{
    __shared__ float Xs[2][128][20];
    __shared__ float Ws[2][128][20];

    const int tid  = threadIdx.x;
    const int wid  = tid >> 5;
    const int lane = tid & 31;
    const int g = lane >> 2;      // group id (rows)
    const int t = lane & 3;       // thread-in-group (cols)
    const int warp_m = wid & 1;
    const int warp_n = wid >> 1;
    const int n0 = blockIdx.x * 128;
    const int m0 = blockIdx.y * 128;

    float acc[4][4][4];
    #pragma unroll
    for (int i = 0; i < 4; i++)
        #pragma unroll
        for (int j = 0; j < 4; j++)
            #pragma unroll
            for (int f = 0; f < 4; f++) acc[i][j][f] = 0.0f;

    const int lrow = tid >> 2;     // 0..63 (x2)
    const int lc4  = tid & 3;

    // prefetch chunk 0
    {
        const float* Xc = X  + (size_t)m0 * D;
        const float* Wc = Wt + (size_t)n0 * D;
        #pragma unroll
        for (int i = 0; i < 2; i++) {
            int row = lrow + i * 64;
            cp_async16(smem_u32(&Xs[0][row][lc4 * 4]), Xc + (size_t)row * D + lc4 * 4);
            cp_async16(smem_u32(&Ws[0][row][lc4 * 4]), Wc + (size_t)row * D + lc4 * 4);
        }
        cp_commit();
    }

    const int NCH = D / LKC;   // 64
    for (int c = 0; c < NCH; c++) {
        const int buf = c & 1;
        if (c + 1 < NCH) {
            const int nb = (c + 1) & 1;
            const float* Xc = X  + (size_t)m0 * D + (c + 1) * LKC;
            const float* Wc = Wt + (size_t)n0 * D + (c + 1) * LKC;
            #pragma unroll
            for (int i = 0; i < 2; i++) {
                int row = lrow + i * 64;
                cp_async16(smem_u32(&Xs[nb][row][lc4 * 4]), Xc + (size_t)row * D + lc4 * 4);
                cp_async16(smem_u32(&Ws[nb][row][lc4 * 4]), Wc + (size_t)row * D + lc4 * 4);
            }
            cp_commit();
            cp_wait1();
        } else {
            cp_wait0();
        }
        __syncthreads();

        #pragma unroll
        for (int ks = 0; ks < 2; ks++) {
            const int kk = ks * 8;
            uint32_t a[4][4];
            #pragma unroll
            for (int mt = 0; mt < 4; mt++) {
                const int r0 = warp_m * 64 + mt * 16;
                a[mt][0] = f2tf32(Xs[buf][r0 + g][kk + t]);
                a[mt][1] = f2tf32(Xs[buf][r0 + 8 + g][kk + t]);
                a[mt][2] = f2tf32(Xs[buf][r0 + g][kk + t + 4]);
                a[mt][3] = f2tf32(Xs[buf][r0 + 8 + g][kk + t + 4]);
            }
            uint32_t bf[4][2];
            #pragma unroll
            for (int nt = 0; nt < 4; nt++) {
                const int nn = warp_n * 32 + nt * 8;
                bf[nt][0] = f2tf32(Ws[buf][nn + g][kk + t]);
                bf[nt][1] = f2tf32(Ws[buf][nn + g][kk + t + 4]);
            }
            #pragma unroll
            for (int mt = 0; mt < 4; mt++)
                #pragma unroll
                for (int nt = 0; nt < 4; nt++)
                    mma8(acc[mt][nt], a[mt], bf[nt]);
        }
        __syncthreads();
    }

    // Epilogue: c0,c1 -> (row, 2t..2t+1), c2,c3 -> (row+8, ...)
    #pragma unroll
    for (int mt = 0; mt < 4; mt++) {
        const int row = m0 + warp_m * 64 + mt * 16 + g;
        #pragma unroll
        for (int nt = 0; nt < 4; nt++) {
            const int col = n0 + warp_n * 32 + nt * 8 + 2 * t;
            float2 bv = *(const float2*)(bias + col);
            float2 o0, o1;
            o0.x = acc[mt][nt][0] + bv.x; o0.y = acc[mt][nt][1] + bv.y;
            o1.x = acc[mt][nt][2] + bv.x; o1.y = acc[mt][nt][3] + bv.y;
            *(float2*)(out + (size_t)row * D + col)       = o0;
            *(float2*)(out + (size_t)(row + 8) * D + col) = o1;
        }
    }
}

// ---------------------------------------------------------------------------
// Flash-style causal attention via mma.sync tf32.
// QT=64 q-rows per CTA, KT=32 keys per tile, 256 threads (8 warps).
// S phase : warp_m = wid&3 (m16 tile), warp_n = wid>>2 (16 cols each).
// PV phase: warp_m = wid&3,            warp_n = wid>>2 (32 d-cols each).
// Smem values are stored tf32-rounded (cvt at global load / softmax store).
// ---------------------------------------------------------------------------
#define QT 64
#define KT 32

__global__ __launch_bounds__(256) void attn_mma_kernel(
    const float* __restrict__ Qp, const float* __restrict__ Kp,
    const float* __restrict__ Vp, float* __restrict__ Ctx)
{
    __shared__ float Qs[QT][68];
    __shared__ float Ks[KT][68];
    __shared__ float Vs[KT][72];
    __shared__ float Ss[QT][33];
    __shared__ float rowm[QT], rowl[QT], rowa[QT];

    const int tid  = threadIdx.x;
    const int wid  = tid >> 5;
    const int lane = tid & 31;
    const int g = lane >> 2;
    const int t = lane & 3;
    const int q0 = blockIdx.x * QT;
    const int h  = blockIdx.y;
    const int b  = blockIdx.z;

    const size_t base = ((size_t)b * S) * D + (size_t)h * DH;

    // Load Q tile (scaled by 1/8, tf32-rounded)
    #pragma unroll
    for (int i = 0; i < 4; i++) {
        int idx = tid + i * 256;      // 1024 float4 slots
        int row = idx >> 4;
        int c4  = idx & 15;
        float4 v = *(const float4*)(Qp + base + (size_t)(q0 + row) * D + c4 * 4);
        Qs[row][c4*4+0] = f2tf32f(v.x * 0.125f);
        Qs[row][c4*4+1] = f2tf32f(v.y * 0.125f);
        Qs[row][c4*4+2] = f2tf32f(v.z * 0.125f);
        Qs[row][c4*4+3] = f2tf32f(v.w * 0.125f);
    }
    if (tid < QT) { rowm[tid] = -1e30f; rowl[tid] = 0.0f; }

    float ctx[4][4];
    #pragma unroll
    for (int i = 0; i < 4; i++)
        #pragma unroll
        for (int j = 0; j < 4; j++) ctx[i][j] = 0.0f;

    const int warp_m = wid & 3;
    const int warp_n = wid >> 2;

    __syncthreads();

    for (int k0 = 0; k0 < q0 + QT; k0 += KT) {
        // Load K,V tiles (tf32-rounded)
        #pragma unroll
        for (int i = 0; i < 2; i++) {
            int idx = tid + i * 256;  // 512 float4 slots
            int row = idx >> 4;
            int c4  = idx & 15;
            float4 kv = *(const float4*)(Kp + base + (size_t)(k0 + row) * D + c4 * 4);
            Ks[row][c4*4+0] = f2tf32f(kv.x); Ks[row][c4*4+1] = f2tf32f(kv.y);
            Ks[row][c4*4+2] = f2tf32f(kv.z); Ks[row][c4*4+3] = f2tf32f(kv.w);
            float4 vv = *(const float4*)(Vp + base + (size_t)(k0 + row) * D + c4 * 4);
            Vs[row][c4*4+0] = f2tf32f(vv.x); Vs[row][c4*4+1] = f2tf32f(vv.y);
            Vs[row][c4*4+2] = f2tf32f(vv.z); Vs[row][c4*4+3] = f2tf32f(vv.w);
        }
        __syncthreads();

        // ---- S = Q @ K^T (warp covers m16 x n16) ----
        {
            float sacc[2][4];
            #pragma unroll
            for (int nt = 0; nt < 2; nt++)
                #pragma unroll
                for (int f = 0; f < 4; f++) sacc[nt][f] = 0.0f;

            #pragma unroll
            for (int d0 = 0; d0 < DH; d0 += 8) {
                uint32_t a[4];
                const int r0 = warp_m * 16;
                a[0] = __float_as_uint(Qs[r0 + g][d0 + t]);
                a[1] = __float_as_uint(Qs[r0 + 8 + g][d0 + t]);
                a[2] = __float_as_uint(Qs[r0 + g][d0 + t + 4]);
                a[3] = __float_as_uint(Qs[r0 + 8 + g][d0 + t + 4]);
                #pragma unroll
                for (int nt = 0; nt < 2; nt++) {
                    const int nb = warp_n * 16 + nt * 8;
                    uint32_t bfr[2];
                    bfr[0] = __float_as_uint(Ks[nb + g][d0 + t]);
                    bfr[1] = __float_as_uint(Ks[nb + g][d0 + t + 4]);
                    mma8(sacc[nt], a, bfr);
                }
            }
            // Store raw scores
            const int r0 = warp_m * 16 + g;
            #pragma unroll
            for (int nt = 0; nt < 2; nt++) {
                const int col = warp_n * 16 + nt * 8 + 2 * t;
                Ss[r0][col]     = sacc[nt][0];
                Ss[r0][col + 1] = sacc[nt][1];
                Ss[r0 + 8][col]     = sacc[nt][2];
                Ss[r0 + 8][col + 1] = sacc[nt][3];
            }
        }
        __syncthreads();

        // ---- Online softmax (threads 0..63, one row each) ----
        if (tid < QT) {
            const int r = tid;
            const int kmax = q0 + r - k0;     // valid cols: c <= kmax
            float mold = rowm[r];
            float mx = mold;
            #pragma unroll
            for (int c = 0; c < KT; c++)
                if (c <= kmax) mx = fmaxf(mx, Ss[r][c]);
            float alpha = __expf(mold - mx);
            float l = rowl[r] * alpha;
            #pragma unroll
            for (int c = 0; c < KT; c++) {
                float p = (c <= kmax) ? __expf(Ss[r][c] - mx) : 0.0f;
                Ss[r][c] = f2tf32f(p);
                l += p;
            }
            rowm[r] = mx; rowl[r] = l; rowa[r] = alpha;
        }
        __syncthreads();

        // ---- ctx = ctx*alpha + P @ V (warp covers m16 x n32) ----
        {
            const float al0 = rowa[warp_m * 16 + g];
            const float al1 = rowa[warp_m * 16 + 8 + g];
            #pragma unroll
            for (int nt = 0; nt < 4; nt++) {
                ctx[nt][0] *= al0; ctx[nt][1] *= al0;
                ctx[nt][2] *= al1; ctx[nt][3] *= al1;
            }
            #pragma unroll
            for (int kk = 0; kk < KT; kk += 8) {
                uint32_t a[4];
                const int r0 = warp_m * 16;
                a[0] = __float_as_uint(Ss[r0 + g][kk + t]);
                a[1] = __float_as_uint(Ss[r0 + 8 + g][kk + t]);
                a[2] = __float_as_uint(Ss[r0 + g][kk + t + 4]);
                a[3] = __float_as_uint(Ss[r0 + 8 + g][kk + t + 4]);
                #pragma unroll
                for (int nt = 0; nt < 4; nt++) {
                    const int nb = warp_n * 32 + nt * 8;
                    uint32_t bfr[2];
                    bfr[0] = __float_as_uint(Vs[kk + t][nb + g]);
                    bfr[1] = __float_as_uint(Vs[kk + t + 4][nb + g]);
                    mma8(ctx[nt], a, bfr);
                }
            }
        }
        __syncthreads();   // protect Ks/Vs/Ss before next tile load
    }

    // Normalize + write out
    {
        const int r0 = warp_m * 16 + g;
        const float linv0 = 1.0f / rowl[r0];
        const float linv1 = 1.0f / rowl[r0 + 8];
        #pragma unroll
        for (int nt = 0; nt < 4; nt++) {
            const int col = warp_n * 32 + nt * 8 + 2 * t;
            float2 o0, o1;
            o0.x = ctx[nt][0] * linv0; o0.y = ctx[nt][1] * linv0;
            o1.x = ctx[nt][2] * linv1; o1.y = ctx[nt][3] * linv1;
            *(float2*)(Ctx + base + (size_t)(q0 + r0) * D + col)     = o0;
            *(float2*)(Ctx + base + (size_t)(q0 + r0 + 8) * D + col) = o1;
        }
    }
}

// ---------------------------------------------------------------------------
// Launch. Inputs: q,k,v,mask,wq,bq,wk,bk,wv,bv,wo,bo
// ---------------------------------------------------------------------------
extern "C" void kernel_launch(void* const* d_in, const int* in_sizes, int n_in,
                              void* d_out, int out_size)
{
    (void)in_sizes; (void)n_in; (void)out_size;
    const float* q  = (const float*)d_in[0];
    const float* k  = (const float*)d_in[1];
    const float* v  = (const float*)d_in[2];
    const float* wq = (const float*)d_in[4];
    const float* bq = (const float*)d_in[5];
    const float* wk = (const float*)d_in[6];
    const float* bk = (const float*)d_in[7];
    const float* wv = (const float*)d_in[8];
    const float* bv = (const float*)d_in[9];
    const float* wo = (const float*)d_in[10];
    const float* bo = (const float*)d_in[11];
    float* out = (float*)d_out;

    float *Qp, *Kp, *Vp, *Ctx;
    cudaGetSymbolAddress((void**)&Qp,  g_Qp);
    cudaGetSymbolAddress((void**)&Kp,  g_Kp);
    cudaGetSymbolAddress((void**)&Vp,  g_Vp);
    cudaGetSymbolAddress((void**)&Ctx, g_Ctx);

    const int M = B * S;                     // 8192
    dim3 gthr(256);
    dim3 ggrid(D / 128, M / 128);            // (8, 64)

    linear_mma_kernel<<<ggrid, gthr>>>(q, wq, bq, Qp);
    linear_mma_kernel<<<ggrid, gthr>>>(k, wk, bk, Kp);
    linear_mma_kernel<<<ggrid, gthr>>>(v, wv, bv, Vp);

    dim3 agrid(S / QT, H, B);                // (32, 16, 4)
    attn_mma_kernel<<<agrid, gthr>>>(Qp, Kp, Vp, Ctx);

    linear_mma_kernel<<<ggrid, gthr>>>(Ctx, wo, bo, out);
}

// round 4
// speedup vs baseline: 3.3230x; 1.3662x over previous
#include <cuda_runtime.h>
#include <cstdint>

#define B 4
#define S 2048
#define D 1024
#define H 16
#define DH 64

// Scratch (allocation-free rule: __device__ globals)
__device__ float g_Qp[B*S*D];
__device__ float g_Kp[B*S*D];
__device__ float g_Vp[B*S*D];
__device__ float g_Ctx[B*S*D];

// ---------------------------------------------------------------------------
// Helpers
// ---------------------------------------------------------------------------
__device__ __forceinline__ uint32_t f2tf32(float f) {
    uint32_t r; asm("cvt.rna.tf32.f32 %0, %1;" : "=r"(r) : "f"(f)); return r;
}
__device__ __forceinline__ float f2tf32f(float f) {
    return __uint_as_float(f2tf32(f));
}
// D = A(16x8) @ B(8x8) + D, tf32 inputs (b32 regs), f32 accum
__device__ __forceinline__ void mma8(float* c, const uint32_t* a, const uint32_t* b) {
    asm volatile(
        "mma.sync.aligned.m16n8k8.row.col.f32.tf32.tf32.f32 "
        "{%0,%1,%2,%3}, {%4,%5,%6,%7}, {%8,%9}, {%0,%1,%2,%3};"
        : "+f"(c[0]), "+f"(c[1]), "+f"(c[2]), "+f"(c[3])
        : "r"(a[0]), "r"(a[1]), "r"(a[2]), "r"(a[3]), "r"(b[0]), "r"(b[1]));
}

// ---------------------------------------------------------------------------
// Linear via mma.sync tf32: out[M,N] = X[M,K] @ W[N,K]^T + bias[N]
// CTA tile 128x128, k-chunk 32 (tf32 stored in smem), register-prefetch
// double buffering. 8 warps: warp_m = wid&1 (64 rows), warp_n = wid>>1.
// ---------------------------------------------------------------------------
#define LKC 32
#define LNCH (D / LKC)   // 32

__global__ __launch_bounds__(256, 2) void linear_mma_kernel(
    const float* __restrict__ X, const float* __restrict__ Wt,
    const float* __restrict__ bias, float* __restrict__ out)
{
    __shared__ float Xs[128][36];
    __shared__ float Ws[128][36];

    const int tid  = threadIdx.x;
    const int wid  = tid >> 5;
    const int lane = tid & 31;
    const int g = lane >> 2;
    const int t = lane & 3;
    const int warp_m = wid & 1;
    const int warp_n = wid >> 1;
    const int n0 = blockIdx.x * 128;
    const int m0 = blockIdx.y * 128;

    float acc[4][4][4];
    #pragma unroll
    for (int i = 0; i < 4; i++)
        #pragma unroll
        for (int j = 0; j < 4; j++)
            #pragma unroll
            for (int f = 0; f < 4; f++) acc[i][j][f] = 0.0f;

    const int row0 = tid >> 3;      // 0..31 (+ i*32)
    const int c4   = tid & 7;       // 0..7  (8 float4 = 32 floats)
    const float* Xbase = X  + (size_t)m0 * D + c4 * 4;
    const float* Wbase = Wt + (size_t)n0 * D + c4 * 4;

    float4 rx[4], rw[4];
    #pragma unroll
    for (int i = 0; i < 4; i++) {
        int row = row0 + i * 32;
        rx[i] = *(const float4*)(Xbase + (size_t)row * D);
        rw[i] = *(const float4*)(Wbase + (size_t)row * D);
    }

    for (int c = 0; c < LNCH; c++) {
        // Store current chunk (cvt once here)
        #pragma unroll
        for (int i = 0; i < 4; i++) {
            int row = row0 + i * 32;
            float4 xv;
            xv.x = f2tf32f(rx[i].x); xv.y = f2tf32f(rx[i].y);
            xv.z = f2tf32f(rx[i].z); xv.w = f2tf32f(rx[i].w);
            *(float4*)&Xs[row][c4 * 4] = xv;
            float4 wv;
            wv.x = f2tf32f(rw[i].x); wv.y = f2tf32f(rw[i].y);
            wv.z = f2tf32f(rw[i].z); wv.w = f2tf32f(rw[i].w);
            *(float4*)&Ws[row][c4 * 4] = wv;
        }
        __syncthreads();

        // Prefetch next chunk (latency hidden by the MMA block below)
        if (c + 1 < LNCH) {
            const float* Xc = Xbase + (size_t)(c + 1) * LKC;
            const float* Wc = Wbase + (size_t)(c + 1) * LKC;
            #pragma unroll
            for (int i = 0; i < 4; i++) {
                int row = row0 + i * 32;
                rx[i] = *(const float4*)(Xc + (size_t)row * D);
                rw[i] = *(const float4*)(Wc + (size_t)row * D);
            }
        }

        #pragma unroll
        for (int ks = 0; ks < 4; ks++) {
            const int kk = ks * 8;
            uint32_t a[4][4];
            #pragma unroll
            for (int mt = 0; mt < 4; mt++) {
                const int r0 = warp_m * 64 + mt * 16;
                a[mt][0] = __float_as_uint(Xs[r0 + g][kk + t]);
                a[mt][1] = __float_as_uint(Xs[r0 + 8 + g][kk + t]);
                a[mt][2] = __float_as_uint(Xs[r0 + g][kk + t + 4]);
                a[mt][3] = __float_as_uint(Xs[r0 + 8 + g][kk + t + 4]);
            }
            uint32_t bf[4][2];
            #pragma unroll
            for (int nt = 0; nt < 4; nt++) {
                const int nn = warp_n * 32 + nt * 8;
                bf[nt][0] = __float_as_uint(Ws[nn + g][kk + t]);
                bf[nt][1] = __float_as_uint(Ws[nn + g][kk + t + 4]);
            }
            #pragma unroll
            for (int mt = 0; mt < 4; mt++)
                #pragma unroll
                for (int nt = 0; nt < 4; nt++)
                    mma8(acc[mt][nt], a[mt], bf[nt]);
        }
        __syncthreads();
    }

    #pragma unroll
    for (int mt = 0; mt < 4; mt++) {
        const int row = m0 + warp_m * 64 + mt * 16 + g;
        #pragma unroll
        for (int nt = 0; nt < 4; nt++) {
            const int col = n0 + warp_n * 32 + nt * 8 + 2 * t;
            float2 bv = *(const float2*)(bias + col);
            float2 o0, o1;
            o0.x = acc[mt][nt][0] + bv.x; o0.y = acc[mt][nt][1] + bv.y;
            o1.x = acc[mt][nt][2] + bv.x; o1.y = acc[mt][nt][3] + bv.y;
            *(float2*)(out + (size_t)row * D + col)       = o0;
            *(float2*)(out + (size_t)(row + 8) * D + col) = o1;
        }
    }
}

// ---------------------------------------------------------------------------
// Flash-style causal attention via mma.sync tf32.
// QT=64 q-rows, KT=64 keys per tile (dyn smem ~71KB, 2 CTA/SM), 8 warps.
// S phase : warp_m = wid&3 (m16), warp_n = wid>>2 (32 of 64 key-cols).
// Softmax : 4 threads per row, interleaved cols, shfl reductions.
// PV phase: warp_m = wid&3 (m16), warp_n = wid>>2 (32 of 64 d-cols).
// ---------------------------------------------------------------------------
#define QT 64
#define KT 64

// dyn smem layout (float offsets)
#define OFF_Q   0                 // [64][68]
#define OFF_K   4352              // [64][68]
#define OFF_V   8704              // [64][72]
#define OFF_S   13312             // [64][68]
#define OFF_RM  17664
#define OFF_RL  17728
#define OFF_RA  17792
#define ATTN_SMEM_FLOATS 17856
#define ATTN_SMEM_BYTES (ATTN_SMEM_FLOATS * 4)

__global__ __launch_bounds__(256, 2) void attn_mma_kernel(
    const float* __restrict__ Qp, const float* __restrict__ Kp,
    const float* __restrict__ Vp, float* __restrict__ Ctx)
{
    extern __shared__ float sm[];
    float* Qs = sm + OFF_Q;     // stride 68
    float* Ks = sm + OFF_K;     // stride 68
    float* Vs = sm + OFF_V;     // stride 72
    float* Ss = sm + OFF_S;     // stride 68
    float* rowm = sm + OFF_RM;
    float* rowl = sm + OFF_RL;
    float* rowa = sm + OFF_RA;

    const int tid  = threadIdx.x;
    const int wid  = tid >> 5;
    const int lane = tid & 31;
    const int g = lane >> 2;
    const int t = lane & 3;
    const int q0 = blockIdx.x * QT;
    const int h  = blockIdx.y;
    const int b  = blockIdx.z;
    const int warp_m = wid & 3;
    const int warp_n = wid >> 2;

    const size_t base = ((size_t)b * S) * D + (size_t)h * DH;

    // Load Q tile (scaled by 1/8, tf32-rounded at store)
    {
        const int row = tid >> 4;    // + i*16
        const int c4  = tid & 15;
        #pragma unroll
        for (int i = 0; i < 4; i++) {
            int r = row + i * 16;
            float4 v = *(const float4*)(Qp + base + (size_t)(q0 + r) * D + c4 * 4);
            float* dst = Qs + r * 68 + c4 * 4;
            dst[0] = f2tf32f(v.x * 0.125f);
            dst[1] = f2tf32f(v.y * 0.125f);
            dst[2] = f2tf32f(v.z * 0.125f);
            dst[3] = f2tf32f(v.w * 0.125f);
        }
    }
    if (tid < QT) { rowm[tid] = -1e30f; rowl[tid] = 0.0f; }

    float ctx[4][4];
    #pragma unroll
    for (int i = 0; i < 4; i++)
        #pragma unroll
        for (int j = 0; j < 4; j++) ctx[i][j] = 0.0f;

    __syncthreads();

    for (int k0 = 0; k0 < q0 + QT; k0 += KT) {
        // ---- Load K,V tiles (64x64 each, tf32-rounded) ----
        {
            const int row = tid >> 4;
            const int c4  = tid & 15;
            #pragma unroll
            for (int i = 0; i < 4; i++) {
                int r = row + i * 16;
                float4 kv = *(const float4*)(Kp + base + (size_t)(k0 + r) * D + c4 * 4);
                float* kd = Ks + r * 68 + c4 * 4;
                kd[0] = f2tf32f(kv.x); kd[1] = f2tf32f(kv.y);
                kd[2] = f2tf32f(kv.z); kd[3] = f2tf32f(kv.w);
                float4 vv = *(const float4*)(Vp + base + (size_t)(k0 + r) * D + c4 * 4);
                float* vd = Vs + r * 72 + c4 * 4;
                vd[0] = f2tf32f(vv.x); vd[1] = f2tf32f(vv.y);
                vd[2] = f2tf32f(vv.z); vd[3] = f2tf32f(vv.w);
            }
        }
        __syncthreads();

        // ---- S = Q @ K^T : warp covers m16 x n32 ----
        {
            float sacc[4][4];
            #pragma unroll
            for (int nt = 0; nt < 4; nt++)
                #pragma unroll
                for (int f = 0; f < 4; f++) sacc[nt][f] = 0.0f;

            const int r0 = warp_m * 16;
            #pragma unroll
            for (int d0 = 0; d0 < DH; d0 += 8) {
                uint32_t a[4];
                a[0] = __float_as_uint(Qs[(r0 + g) * 68 + d0 + t]);
                a[1] = __float_as_uint(Qs[(r0 + 8 + g) * 68 + d0 + t]);
                a[2] = __float_as_uint(Qs[(r0 + g) * 68 + d0 + t + 4]);
                a[3] = __float_as_uint(Qs[(r0 + 8 + g) * 68 + d0 + t + 4]);
                #pragma unroll
                for (int nt = 0; nt < 4; nt++) {
                    const int nb = warp_n * 32 + nt * 8;
                    uint32_t bfr[2];
                    bfr[0] = __float_as_uint(Ks[(nb + g) * 68 + d0 + t]);
                    bfr[1] = __float_as_uint(Ks[(nb + g) * 68 + d0 + t + 4]);
                    mma8(sacc[nt], a, bfr);
                }
            }
            const int rr = r0 + g;
            #pragma unroll
            for (int nt = 0; nt < 4; nt++) {
                const int col = warp_n * 32 + nt * 8 + 2 * t;
                *(float2*)&Ss[rr * 68 + col]       = make_float2(sacc[nt][0], sacc[nt][1]);
                *(float2*)&Ss[(rr + 8) * 68 + col] = make_float2(sacc[nt][2], sacc[nt][3]);
            }
        }
        __syncthreads();

        // ---- Online softmax: 4 threads per row, interleaved cols ----
        {
            const int r   = tid >> 2;    // 0..63
            const int sgl = tid & 3;
            const int kmax = q0 + r - k0;      // valid cols: c <= kmax
            const float mold = rowm[r];
            float mx = mold;
            float vals[16];
            #pragma unroll
            for (int j = 0; j < 16; j++) {
                int c = sgl + 4 * j;
                float v = (c <= kmax) ? Ss[r * 68 + c] : -1e30f;
                vals[j] = v;
                mx = fmaxf(mx, v);
            }
            mx = fmaxf(mx, __shfl_xor_sync(0xFFFFFFFFu, mx, 1));
            mx = fmaxf(mx, __shfl_xor_sync(0xFFFFFFFFu, mx, 2));
            float l = 0.0f;
            #pragma unroll
            for (int j = 0; j < 16; j++) {
                int c = sgl + 4 * j;
                float p = (vals[j] > -1e29f) ? __expf(vals[j] - mx) : 0.0f;
                Ss[r * 68 + c] = f2tf32f(p);
                l += p;
            }
            l += __shfl_xor_sync(0xFFFFFFFFu, l, 1);
            l += __shfl_xor_sync(0xFFFFFFFFu, l, 2);
            if (sgl == 0) {
                float alpha = __expf(mold - mx);
                rowa[r] = alpha;
                rowl[r] = rowl[r] * alpha + l;
                rowm[r] = mx;
            }
        }
        __syncthreads();

        // ---- ctx = ctx*alpha + P @ V : warp covers m16 x n32 (d cols) ----
        {
            const int r0 = warp_m * 16;
            const float al0 = rowa[r0 + g];
            const float al1 = rowa[r0 + 8 + g];
            #pragma unroll
            for (int nt = 0; nt < 4; nt++) {
                ctx[nt][0] *= al0; ctx[nt][1] *= al0;
                ctx[nt][2] *= al1; ctx[nt][3] *= al1;
            }
            #pragma unroll
            for (int kk = 0; kk < KT; kk += 8) {
                uint32_t a[4];
                a[0] = __float_as_uint(Ss[(r0 + g) * 68 + kk + t]);
                a[1] = __float_as_uint(Ss[(r0 + 8 + g) * 68 + kk + t]);
                a[2] = __float_as_uint(Ss[(r0 + g) * 68 + kk + t + 4]);
                a[3] = __float_as_uint(Ss[(r0 + 8 + g) * 68 + kk + t + 4]);
                #pragma unroll
                for (int nt = 0; nt < 4; nt++) {
                    const int nb = warp_n * 32 + nt * 8;
                    uint32_t bfr[2];
                    bfr[0] = __float_as_uint(Vs[(kk + t) * 72 + nb + g]);
                    bfr[1] = __float_as_uint(Vs[(kk + t + 4) * 72 + nb + g]);
                    mma8(ctx[nt], a, bfr);
                }
            }
        }
        __syncthreads();   // protect Ks/Vs/Ss before next tile load
    }

    // Normalize + write out
    {
        const int r0 = warp_m * 16 + g;
        const float linv0 = 1.0f / rowl[r0];
        const float linv1 = 1.0f / rowl[r0 + 8];
        #pragma unroll
        for (int nt = 0; nt < 4; nt++) {
            const int col = warp_n * 32 + nt * 8 + 2 * t;
            float2 o0, o1;
            o0.x = ctx[nt][0] * linv0; o0.y = ctx[nt][1] * linv0;
            o1.x = ctx[nt][2] * linv1; o1.y = ctx[nt][3] * linv1;
            *(float2*)(Ctx + base + (size_t)(q0 + r0) * D + col)     = o0;
            *(float2*)(Ctx + base + (size_t)(q0 + r0 + 8) * D + col) = o1;
        }
    }
}

// ---------------------------------------------------------------------------
// Launch. Inputs: q,k,v,mask,wq,bq,wk,bk,wv,bv,wo,bo
// ---------------------------------------------------------------------------
extern "C" void kernel_launch(void* const* d_in, const int* in_sizes, int n_in,
                              void* d_out, int out_size)
{
    (void)in_sizes; (void)n_in; (void)out_size;
    const float* q  = (const float*)d_in[0];
    const float* k  = (const float*)d_in[1];
    const float* v  = (const float*)d_in[2];
    const float* wq = (const float*)d_in[4];
    const float* bq = (const float*)d_in[5];
    const float* wk = (const float*)d_in[6];
    const float* bk = (const float*)d_in[7];
    const float* wv = (const float*)d_in[8];
    const float* bv = (const float*)d_in[9];
    const float* wo = (const float*)d_in[10];
    const float* bo = (const float*)d_in[11];
    float* out = (float*)d_out;

    float *Qp, *Kp, *Vp, *Ctx;
    cudaGetSymbolAddress((void**)&Qp,  g_Qp);
    cudaGetSymbolAddress((void**)&Kp,  g_Kp);
    cudaGetSymbolAddress((void**)&Vp,  g_Vp);
    cudaGetSymbolAddress((void**)&Ctx, g_Ctx);

    cudaFuncSetAttribute(attn_mma_kernel,
                         cudaFuncAttributeMaxDynamicSharedMemorySize, ATTN_SMEM_BYTES);

    const int M = B * S;                     // 8192
    dim3 gthr(256);
    dim3 ggrid(D / 128, M / 128);            // (8, 64)

    linear_mma_kernel<<<ggrid, gthr>>>(q, wq, bq, Qp);
    linear_mma_kernel<<<ggrid, gthr>>>(k, wk, bk, Kp);
    linear_mma_kernel<<<ggrid, gthr>>>(v, wv, bv, Vp);

    dim3 agrid(S / QT, H, B);                // (32, 16, 4)
    attn_mma_kernel<<<agrid, gthr, ATTN_SMEM_BYTES>>>(Qp, Kp, Vp, Ctx);

    linear_mma_kernel<<<ggrid, gthr>>>(Ctx, wo, bo, out);
}